// round 13
// baseline (speedup 1.0000x reference)
#include <cuda_runtime.h>
#include <cstdint>

#define BATCH 32
#define T     1024
#define DIN   512
#define DH    512
#define M_TOT (BATCH * T)   // 32768

// scratch: tf32-rounded A (64MB), rounded W (1MB), X~ (64MB)
__device__ float g_A[(size_t)M_TOT * DIN];
__device__ float g_Wt[(size_t)DH * DIN];
__device__ float g_X[(size_t)M_TOT * DH];

#define WLCAP 262144
__device__ int g_cnt;
__device__ int g_wl[WLCAP];

#define DELTA 1.4e-3f

// ---------------------------------------------------------------------------
__device__ __forceinline__ uint32_t smem_u32(const void* p) {
    uint32_t a;
    asm("{ .reg .u64 t; cvta.to.shared.u64 t, %1; cvt.u32.u64 %0, t; }"
        : "=r"(a) : "l"(p));
    return a;
}
#define CP_ASYNC16(sa, gp) \
    asm volatile("cp.async.cg.shared.global [%0], [%1], 16;" :: "r"(sa), "l"(gp))
#define CP_COMMIT() asm volatile("cp.async.commit_group;" ::: "memory")
#define CP_WAIT(n)  asm volatile("cp.async.wait_group %0;" :: "n"(n) : "memory")

__device__ __forceinline__ float cvt_tf32(float x) {
    uint32_t b;
    asm("cvt.rna.tf32.f32 %0, %1;" : "=r"(b) : "f"(x));
    return __uint_as_float(b);
}
__device__ __forceinline__ void mma_tf32(float c[4], const float a[4], const float b[2]) {
    asm volatile(
        "mma.sync.aligned.m16n8k8.row.col.f32.tf32.tf32.f32 "
        "{%0,%1,%2,%3}, {%4,%5,%6,%7}, {%8,%9}, {%0,%1,%2,%3};"
        : "+f"(c[0]), "+f"(c[1]), "+f"(c[2]), "+f"(c[3])
        : "r"(__float_as_uint(a[0])), "r"(__float_as_uint(a[1])),
          "r"(__float_as_uint(a[2])), "r"(__float_as_uint(a[3])),
          "r"(__float_as_uint(b[0])), "r"(__float_as_uint(b[1])));
}

__global__ void zero_cnt() { g_cnt = 0; }

// ---------------------------------------------------------------------------
// prep: round to tf32 (RN) once, so the GEMM inner loop has no cvt ops and
// the quantization is unbiased.
// ---------------------------------------------------------------------------
__global__ __launch_bounds__(256)
void prep_in(const float* __restrict__ A)
{
    size_t i = ((size_t)blockIdx.x * 256 + threadIdx.x) * 4;
    float4 v = *(const float4*)(A + i);
    v.x = cvt_tf32(v.x); v.y = cvt_tf32(v.y);
    v.z = cvt_tf32(v.z); v.w = cvt_tf32(v.w);
    *(float4*)(g_A + i) = v;
}
__global__ __launch_bounds__(256)
void prep_w(const float* __restrict__ W)
{
    size_t i = ((size_t)blockIdx.x * 256 + threadIdx.x) * 4;
    float4 v = *(const float4*)(W + i);
    v.x = cvt_tf32(v.x); v.y = cvt_tf32(v.y);
    v.z = cvt_tf32(v.z); v.w = cvt_tf32(v.w);
    *(float4*)(g_Wt + i) = v;
}

// ---------------------------------------------------------------------------
// Single-pass tf32 GEMM: X~[m,n] = sum_k A[m,k]*W[n,k] + bias[n]
// 128x128 CTA tile, 8 warps (2x4), warp 64x32, K-chunk 32, double buffer.
// One m16n8k8 MMA per (i,j) per k8-step -> 8.6G MACs total, tensor-pipe bound.
// ---------------------------------------------------------------------------
#define BK      32
#define NCHUNK  (DIN / BK)
#define SROW    36
#define A_OFF   0
#define B_OFF   (128 * SROW)
#define BUF_FL  (2 * 128 * SROW)
#define SMEM_BYTES (2 * BUF_FL * 4)   // 73728

__device__ __forceinline__ void issue_chunk(uint32_t sbuf, int bm, int bn,
                                            int k0, int tid)
{
#pragma unroll
    for (int q = 0; q < 4; q++) {
        int u   = tid + q * 256;
        int row = u >> 3;
        int seg = u & 7;
        CP_ASYNC16(sbuf + A_OFF * 4 + row * (SROW * 4) + seg * 16,
                   g_A + (size_t)(bm + row) * DIN + k0 + seg * 4);
        CP_ASYNC16(sbuf + B_OFF * 4 + row * (SROW * 4) + seg * 16,
                   g_Wt + (size_t)(bn + row) * DIN + k0 + seg * 4);
    }
}

__global__ __launch_bounds__(256, 2)
void gemm_tf32(const float* __restrict__ bias, float* __restrict__ X)
{
    extern __shared__ float sm[];
    const int tid  = threadIdx.x;
    const int lane = tid & 31;
    const int wid  = tid >> 5;
    const int g    = lane >> 2;
    const int tg   = lane & 3;
    const int wm   = wid >> 2;      // 0..1
    const int wn   = wid & 3;       // 0..3
    const int bm   = blockIdx.x * 128;
    const int bn   = blockIdx.y * 128;

    const uint32_t sb0 = smem_u32(sm);

    float acc[4][4][4];
#pragma unroll
    for (int i = 0; i < 4; i++)
#pragma unroll
        for (int j = 0; j < 4; j++)
#pragma unroll
            for (int r = 0; r < 4; r++) acc[i][j][r] = 0.0f;

    issue_chunk(sb0, bm, bn, 0, tid);
    CP_COMMIT();

    for (int c = 0; c < NCHUNK; c++) {
        if (c + 1 < NCHUNK) {
            issue_chunk(sb0 + ((c + 1) & 1) * (BUF_FL * 4), bm, bn,
                        (c + 1) * BK, tid);
            CP_COMMIT();
            CP_WAIT(1);
        } else {
            CP_WAIT(0);
        }
        __syncthreads();

        const float* As = sm + (c & 1) * BUF_FL + A_OFF;
        const float* Bs = sm + (c & 1) * BUF_FL + B_OFF;

#pragma unroll
        for (int ks = 0; ks < 4; ks++) {
            const int kk = ks * 8;
            float a[4][4], b[4][2];
#pragma unroll
            for (int i = 0; i < 4; i++) {
                int row = wm * 64 + i * 16 + g;
                a[i][0] = As[(row     ) * SROW + kk + tg    ];
                a[i][1] = As[(row +  8) * SROW + kk + tg    ];
                a[i][2] = As[(row     ) * SROW + kk + tg + 4];
                a[i][3] = As[(row +  8) * SROW + kk + tg + 4];
            }
#pragma unroll
            for (int j = 0; j < 4; j++) {
                int n = wn * 32 + j * 8 + g;
                b[j][0] = Bs[n * SROW + kk + tg    ];
                b[j][1] = Bs[n * SROW + kk + tg + 4];
            }
#pragma unroll
            for (int i = 0; i < 4; i++)
#pragma unroll
                for (int j = 0; j < 4; j++)
                    mma_tf32(acc[i][j], a[i], b[j]);
        }
        __syncthreads();
    }

#pragma unroll
    for (int j = 0; j < 4; j++) {
        int col = bn + wn * 32 + j * 8 + tg * 2;
        float b0 = bias[col], b1 = bias[col + 1];
#pragma unroll
        for (int i = 0; i < 4; i++) {
            int row = bm + wm * 64 + i * 16 + g;
            float2 v0 = { acc[i][j][0] + b0, acc[i][j][1] + b1 };
            float2 v1 = { acc[i][j][2] + b0, acc[i][j][3] + b1 };
            *(float2*)(X + (size_t)row * DH + col)       = v0;
            *(float2*)(X + (size_t)(row + 8) * DH + col) = v1;
        }
    }
}

// ---------------------------------------------------------------------------
// Chunk-parallel scan on X~ with threshold + borderline flagging.
// ---------------------------------------------------------------------------
__global__ __launch_bounds__(256)
void scan2f(const float* __restrict__ X, const float* __restrict__ thr_p,
            float* __restrict__ out)
{
    const int bc    = blockIdx.x;
    const int b     = bc >> 4;
    const int chunk = (bc >> 1) & 7;
    const int half  = bc & 1;
    const int h     = half * 256 + threadIdx.x;

    const float AL  = 0.36787944117144233f;
    const float OMB = 1.0f - AL;
    const float thr = thr_p[0];

    const float* xp = X   + (size_t)b * T * DH + h;
    float*       op = out + (size_t)b * T * DH + h;

    const int t0 = chunk * 128;
    const int w0 = (t0 >= 96) ? (t0 - 96) : 0;
    const int base_lin = (b * T) * DH + h;

    float s = 0.0f, m = 0.0f;

    for (int t = w0; t < t0; t += 8) {
        float x[8];
#pragma unroll
        for (int u = 0; u < 8; u++) x[u] = xp[(size_t)(t + u) * DH];
#pragma unroll
        for (int u = 0; u < 8; u++) {
            s = fmaf(AL, s, x[u]);
            m = fmaf(AL, m, OMB * s);
        }
    }
    for (int t = t0; t < t0 + 128; t += 8) {
        float x[8], sp[8];
#pragma unroll
        for (int u = 0; u < 8; u++) x[u] = xp[(size_t)(t + u) * DH];
#pragma unroll
        for (int u = 0; u < 8; u++) {
            s = fmaf(AL, s, x[u]);
            m = fmaf(AL, m, OMB * s);
            float d = m - thr;
            sp[u] = (d > 0.0f) ? 1.0f : 0.0f;
            if (fabsf(d) < DELTA) {
                int idx = atomicAdd(&g_cnt, 1);
                if (idx < WLCAP) g_wl[idx] = base_lin + (t + u) * DH;
            }
        }
#pragma unroll
        for (int u = 0; u < 8; u++) op[(size_t)(t + u) * DH] = sp[u];
    }
}

// ---------------------------------------------------------------------------
// Patch: recompute flagged elements with the R1-exact float-op sequence
// (validated bitwise-equal to the R1 baseline in round 8).
// ---------------------------------------------------------------------------
__global__ __launch_bounds__(256)
void patch(const float* __restrict__ X, const float* __restrict__ W,
           const float* __restrict__ bias, const float* __restrict__ thr_p,
           float* __restrict__ OUT)
{
    const int nwarp = gridDim.x * 8;
    const int w     = blockIdx.x * 8 + (threadIdx.x >> 5);
    const int lane  = threadIdx.x & 31;
    const int cnt   = min(g_cnt, WLCAP);

    const float AL  = 0.36787944117144233f;
    const float OMB = 1.0f - AL;
    const float thr = thr_p[0];

    for (int it = w; it < cnt; it += nwarp) {
        int lin = g_wl[it];
        int h  = lin & (DH - 1);
        int bt = lin >> 9;
        int t  = bt & (T - 1);
        int b  = bt >> 10;

        int tw = (t >= 80) ? (t - 80) : 0;
        int nT = t - tw + 1;   // <= 81

        const float* wrow = W + (size_t)h * DIN;
        float bh = bias[h];

        float acc[3] = {0.0f, 0.0f, 0.0f};
        const float* ip[3];
#pragma unroll
        for (int u = 0; u < 3; u++) {
            int tp = tw + lane + u * 32;
            int tsafe = (tp <= t) ? tp : t;
            ip[u] = X + ((size_t)b * T + tsafe) * DIN;
        }
        for (int k = 0; k < DIN; k += 4) {
            float4 w4 = *(const float4*)(wrow + k);
#pragma unroll
            for (int u = 0; u < 3; u++) {
                float4 a4 = *(const float4*)(ip[u] + k);
                acc[u] = fmaf(a4.x, w4.x, acc[u]);
                acc[u] = fmaf(a4.y, w4.y, acc[u]);
                acc[u] = fmaf(a4.z, w4.z, acc[u]);
                acc[u] = fmaf(a4.w, w4.w, acc[u]);
            }
        }
        float xv[3];
#pragma unroll
        for (int u = 0; u < 3; u++) xv[u] = acc[u] + bh;

        float s = 0.0f, m = 0.0f;
        for (int q = 0; q < nT; q++) {
            float x0 = __shfl_sync(0xFFFFFFFFu, xv[0], q & 31);
            float x1 = __shfl_sync(0xFFFFFFFFu, xv[1], q & 31);
            float x2 = __shfl_sync(0xFFFFFFFFu, xv[2], q & 31);
            float x = (q < 32) ? x0 : ((q < 64) ? x1 : x2);
            s = fmaf(AL, s, x);
            m = fmaf(AL, m, OMB * s);
        }
        if (lane == 0)
            OUT[lin] = (m > thr) ? 1.0f : 0.0f;
    }
}

// ---------------------------------------------------------------------------
extern "C" void kernel_launch(void* const* d_in, const int* in_sizes, int n_in,
                              void* d_out, int out_size)
{
    const float* inputs = (const float*)d_in[0];
    const float* W      = (const float*)d_in[1];
    const float* bias   = (const float*)d_in[2];
    const float* thr    = (const float*)d_in[3];
    float*       out    = (float*)d_out;

    float* Xs;
    cudaGetSymbolAddress((void**)&Xs, g_X);

    cudaFuncSetAttribute(gemm_tf32, cudaFuncAttributeMaxDynamicSharedMemorySize, SMEM_BYTES);

    zero_cnt<<<1, 1>>>();
    prep_in<<<(M_TOT * DIN) / 1024, 256>>>(inputs);
    prep_w<<<(DH * DIN) / 1024, 256>>>(W);

    dim3 ggrid(M_TOT / 128, DH / 128);   // (256, 4)
    gemm_tf32<<<ggrid, 256, SMEM_BYTES>>>(bias, Xs);

    scan2f<<<512, 256>>>(Xs, thr, out);
    patch<<<256, 256>>>(inputs, W, bias, thr, out);
}

// round 14
// speedup vs baseline: 1.3874x; 1.3874x over previous
#include <cuda_runtime.h>
#include <cstdint>

#define BATCH 32
#define T     1024
#define DIN   512
#define DH    512
#define M_TOT (BATCH * T)   // 32768

// scratch: tf32-rounded A (64MB), rounded W (1MB), X~ (64MB)
__device__ float g_A[(size_t)M_TOT * DIN];
__device__ float g_Wt[(size_t)DH * DIN];
__device__ float g_X[(size_t)M_TOT * DH];

#define WLCAP 262144
__device__ int g_cnt;
__device__ int g_wl[WLCAP];

#define DELTA 1.4e-3f

// ---------------------------------------------------------------------------
__device__ __forceinline__ uint32_t smem_u32(const void* p) {
    uint32_t a;
    asm("{ .reg .u64 t; cvta.to.shared.u64 t, %1; cvt.u32.u64 %0, t; }"
        : "=r"(a) : "l"(p));
    return a;
}
#define CP_ASYNC16(sa, gp) \
    asm volatile("cp.async.cg.shared.global [%0], [%1], 16;" :: "r"(sa), "l"(gp))
#define CP_COMMIT() asm volatile("cp.async.commit_group;" ::: "memory")
#define CP_WAIT(n)  asm volatile("cp.async.wait_group %0;" :: "n"(n) : "memory")

__device__ __forceinline__ float cvt_tf32(float x) {
    uint32_t b;
    asm("cvt.rna.tf32.f32 %0, %1;" : "=r"(b) : "f"(x));
    return __uint_as_float(b);
}
__device__ __forceinline__ void mma_tf32(float c[4], const float a[4], const float b[2]) {
    asm volatile(
        "mma.sync.aligned.m16n8k8.row.col.f32.tf32.tf32.f32 "
        "{%0,%1,%2,%3}, {%4,%5,%6,%7}, {%8,%9}, {%0,%1,%2,%3};"
        : "+f"(c[0]), "+f"(c[1]), "+f"(c[2]), "+f"(c[3])
        : "r"(__float_as_uint(a[0])), "r"(__float_as_uint(a[1])),
          "r"(__float_as_uint(a[2])), "r"(__float_as_uint(a[3])),
          "r"(__float_as_uint(b[0])), "r"(__float_as_uint(b[1])));
}

__global__ void zero_cnt() { g_cnt = 0; }

// ---------------------------------------------------------------------------
// prep: round to tf32 (RN) once (unbiased; keeps GEMM inner loop cvt-free)
// ---------------------------------------------------------------------------
__global__ __launch_bounds__(256)
void prep_in(const float* __restrict__ A)
{
    size_t i = ((size_t)blockIdx.x * 256 + threadIdx.x) * 4;
    float4 v = *(const float4*)(A + i);
    v.x = cvt_tf32(v.x); v.y = cvt_tf32(v.y);
    v.z = cvt_tf32(v.z); v.w = cvt_tf32(v.w);
    *(float4*)(g_A + i) = v;
}
__global__ __launch_bounds__(256)
void prep_w(const float* __restrict__ W)
{
    size_t i = ((size_t)blockIdx.x * 256 + threadIdx.x) * 4;
    float4 v = *(const float4*)(W + i);
    v.x = cvt_tf32(v.x); v.y = cvt_tf32(v.y);
    v.z = cvt_tf32(v.z); v.w = cvt_tf32(v.w);
    *(float4*)(g_Wt + i) = v;
}

// ---------------------------------------------------------------------------
// Single-pass tf32 GEMM: X~[m,n] = sum_k A[m,k]*W[n,k] + bias[n]
// 128x128 CTA tile, 8 warps (2x4), warp 64x32, K-chunk 32, double buffer.
// ---------------------------------------------------------------------------
#define BK      32
#define NCHUNK  (DIN / BK)
#define SROW    36
#define A_OFF   0
#define B_OFF   (128 * SROW)
#define BUF_FL  (2 * 128 * SROW)
#define SMEM_BYTES (2 * BUF_FL * 4)   // 73728

__device__ __forceinline__ void issue_chunk(uint32_t sbuf, int bm, int bn,
                                            int k0, int tid)
{
#pragma unroll
    for (int q = 0; q < 4; q++) {
        int u   = tid + q * 256;
        int row = u >> 3;
        int seg = u & 7;
        CP_ASYNC16(sbuf + A_OFF * 4 + row * (SROW * 4) + seg * 16,
                   g_A + (size_t)(bm + row) * DIN + k0 + seg * 4);
        CP_ASYNC16(sbuf + B_OFF * 4 + row * (SROW * 4) + seg * 16,
                   g_Wt + (size_t)(bn + row) * DIN + k0 + seg * 4);
    }
}

__global__ __launch_bounds__(256, 2)
void gemm_tf32(const float* __restrict__ bias, float* __restrict__ X)
{
    extern __shared__ float sm[];
    const int tid  = threadIdx.x;
    const int lane = tid & 31;
    const int wid  = tid >> 5;
    const int g    = lane >> 2;
    const int tg   = lane & 3;
    const int wm   = wid >> 2;
    const int wn   = wid & 3;
    const int bm   = blockIdx.x * 128;
    const int bn   = blockIdx.y * 128;

    const uint32_t sb0 = smem_u32(sm);

    float acc[4][4][4];
#pragma unroll
    for (int i = 0; i < 4; i++)
#pragma unroll
        for (int j = 0; j < 4; j++)
#pragma unroll
            for (int r = 0; r < 4; r++) acc[i][j][r] = 0.0f;

    issue_chunk(sb0, bm, bn, 0, tid);
    CP_COMMIT();

    for (int c = 0; c < NCHUNK; c++) {
        if (c + 1 < NCHUNK) {
            issue_chunk(sb0 + ((c + 1) & 1) * (BUF_FL * 4), bm, bn,
                        (c + 1) * BK, tid);
            CP_COMMIT();
            CP_WAIT(1);
        } else {
            CP_WAIT(0);
        }
        __syncthreads();

        const float* As = sm + (c & 1) * BUF_FL + A_OFF;
        const float* Bs = sm + (c & 1) * BUF_FL + B_OFF;

#pragma unroll
        for (int ks = 0; ks < 4; ks++) {
            const int kk = ks * 8;
            float a[4][4], b[4][2];
#pragma unroll
            for (int i = 0; i < 4; i++) {
                int row = wm * 64 + i * 16 + g;
                a[i][0] = As[(row     ) * SROW + kk + tg    ];
                a[i][1] = As[(row +  8) * SROW + kk + tg    ];
                a[i][2] = As[(row     ) * SROW + kk + tg + 4];
                a[i][3] = As[(row +  8) * SROW + kk + tg + 4];
            }
#pragma unroll
            for (int j = 0; j < 4; j++) {
                int n = wn * 32 + j * 8 + g;
                b[j][0] = Bs[n * SROW + kk + tg    ];
                b[j][1] = Bs[n * SROW + kk + tg + 4];
            }
#pragma unroll
            for (int i = 0; i < 4; i++)
#pragma unroll
                for (int j = 0; j < 4; j++)
                    mma_tf32(acc[i][j], a[i], b[j]);
        }
        __syncthreads();
    }

#pragma unroll
    for (int j = 0; j < 4; j++) {
        int col = bn + wn * 32 + j * 8 + tg * 2;
        float b0 = bias[col], b1 = bias[col + 1];
#pragma unroll
        for (int i = 0; i < 4; i++) {
            int row = bm + wm * 64 + i * 16 + g;
            float2 v0 = { acc[i][j][0] + b0, acc[i][j][1] + b1 };
            float2 v1 = { acc[i][j][2] + b0, acc[i][j][3] + b1 };
            *(float2*)(X + (size_t)row * DH + col)       = v0;
            *(float2*)(X + (size_t)(row + 8) * DH + col) = v1;
        }
    }
}

// ---------------------------------------------------------------------------
// Chunk-parallel scan on X~ with threshold + borderline flagging.
// ---------------------------------------------------------------------------
__global__ __launch_bounds__(256)
void scan2f(const float* __restrict__ X, const float* __restrict__ thr_p,
            float* __restrict__ out)
{
    const int bc    = blockIdx.x;
    const int b     = bc >> 4;
    const int chunk = (bc >> 1) & 7;
    const int half  = bc & 1;
    const int h     = half * 256 + threadIdx.x;

    const float AL  = 0.36787944117144233f;
    const float OMB = 1.0f - AL;
    const float thr = thr_p[0];

    const float* xp = X   + (size_t)b * T * DH + h;
    float*       op = out + (size_t)b * T * DH + h;

    const int t0 = chunk * 128;
    const int w0 = (t0 >= 96) ? (t0 - 96) : 0;
    const int base_lin = (b * T) * DH + h;

    float s = 0.0f, m = 0.0f;

    for (int t = w0; t < t0; t += 8) {
        float x[8];
#pragma unroll
        for (int u = 0; u < 8; u++) x[u] = xp[(size_t)(t + u) * DH];
#pragma unroll
        for (int u = 0; u < 8; u++) {
            s = fmaf(AL, s, x[u]);
            m = fmaf(AL, m, OMB * s);
        }
    }
    for (int t = t0; t < t0 + 128; t += 8) {
        float x[8], sp[8];
#pragma unroll
        for (int u = 0; u < 8; u++) x[u] = xp[(size_t)(t + u) * DH];
#pragma unroll
        for (int u = 0; u < 8; u++) {
            s = fmaf(AL, s, x[u]);
            m = fmaf(AL, m, OMB * s);
            float d = m - thr;
            sp[u] = (d > 0.0f) ? 1.0f : 0.0f;
            if (fabsf(d) < DELTA) {
                int idx = atomicAdd(&g_cnt, 1);
                if (idx < WLCAP) g_wl[idx] = base_lin + (t + u) * DH;
            }
        }
#pragma unroll
        for (int u = 0; u < 8; u++) op[(size_t)(t + u) * DH] = sp[u];
    }
}

// ---------------------------------------------------------------------------
// Patch: recompute flagged elements with the R1-exact float-op sequence
// (bitwise-validated mechanism, R8). One WARP per item, k-tiled through smem:
// coalesced GMEM loads, conflict-free LDS (row stride 68 words, 16B aligned),
// serial fmaf chains per lane preserve R1's exact k-ascending order.
// ---------------------------------------------------------------------------
#define PROWS 84     // >= 81 rows
#define PSTR  68     // floats per smem row (64 + 4; 272B = 16B aligned)

__global__ __launch_bounds__(32)
void patch(const float* __restrict__ X, const float* __restrict__ W,
           const float* __restrict__ bias, const float* __restrict__ thr_p,
           float* __restrict__ OUT)
{
    __shared__ __align__(16) float As[PROWS * PSTR];   // 22848 B
    __shared__ __align__(16) float Ws[DIN];            // 2048 B

    const int lane = threadIdx.x;
    const int cnt  = min(g_cnt, WLCAP);

    const float AL  = 0.36787944117144233f;
    const float OMB = 1.0f - AL;
    const float thr = thr_p[0];

    for (int it = blockIdx.x; it < cnt; it += gridDim.x) {
        int lin = g_wl[it];
        int h  = lin & (DH - 1);
        int bt = lin >> 9;
        int t  = bt & (T - 1);
        int b  = bt >> 10;

        int tw = (t >= 80) ? (t - 80) : 0;
        int nT = t - tw + 1;   // <= 81

        // stage W row (coalesced)
#pragma unroll
        for (int q = 0; q < 4; q++) {
            int k = q * 128 + lane * 4;
            *(float4*)&Ws[k] = *(const float4*)(W + (size_t)h * DIN + k);
        }
        float bh = bias[h];

        // each lane owns dots for time rows lane, lane+32, lane+64 (clamped)
        int r_ln[3];
#pragma unroll
        for (int u = 0; u < 3; u++) {
            int tp = tw + lane + u * 32;
            r_ln[u] = ((tp <= t) ? tp : t) - tw;
        }

        float acc[3] = {0.0f, 0.0f, 0.0f};
        const float* xbase = X + ((size_t)b * T + tw) * DIN;

        for (int kt = 0; kt < 8; kt++) {
            __syncwarp();
            // coalesced load of nT row-segments (64 floats each) into smem
            for (int u = lane; u < nT * 16; u += 32) {
                int r = u >> 4, cc = u & 15;
                *(float4*)&As[r * PSTR + cc * 4] =
                    *(const float4*)(xbase + (size_t)r * DIN + kt * 64 + cc * 4);
            }
            __syncwarp();
            // serial fmaf chains (R1 order: k ascending, .x .y .z .w)
#pragma unroll
            for (int u = 0; u < 3; u++) {
                const float* ar = &As[r_ln[u] * PSTR];
                const float* wr = &Ws[kt * 64];
                float a = acc[u];
#pragma unroll
                for (int c = 0; c < 16; c++) {
                    float4 a4 = *(const float4*)&ar[c * 4];
                    float4 w4 = *(const float4*)&wr[c * 4];
                    a = fmaf(a4.x, w4.x, a);
                    a = fmaf(a4.y, w4.y, a);
                    a = fmaf(a4.z, w4.z, a);
                    a = fmaf(a4.w, w4.w, a);
                }
                acc[u] = a;
            }
        }

        float xv[3];
#pragma unroll
        for (int u = 0; u < 3; u++) xv[u] = acc[u] + bh;

        // exact scan over tw..t (all lanes redundantly; shfl distributes xv)
        float s = 0.0f, m = 0.0f;
        for (int q = 0; q < nT; q++) {
            float x0 = __shfl_sync(0xFFFFFFFFu, xv[0], q & 31);
            float x1 = __shfl_sync(0xFFFFFFFFu, xv[1], q & 31);
            float x2 = __shfl_sync(0xFFFFFFFFu, xv[2], q & 31);
            float x = (q < 32) ? x0 : ((q < 64) ? x1 : x2);
            s = fmaf(AL, s, x);
            m = fmaf(AL, m, OMB * s);
        }
        if (lane == 0)
            OUT[lin] = (m > thr) ? 1.0f : 0.0f;
        __syncwarp();
    }
}

// ---------------------------------------------------------------------------
extern "C" void kernel_launch(void* const* d_in, const int* in_sizes, int n_in,
                              void* d_out, int out_size)
{
    const float* inputs = (const float*)d_in[0];
    const float* W      = (const float*)d_in[1];
    const float* bias   = (const float*)d_in[2];
    const float* thr    = (const float*)d_in[3];
    float*       out    = (float*)d_out;

    float* Xs;
    cudaGetSymbolAddress((void**)&Xs, g_X);

    cudaFuncSetAttribute(gemm_tf32, cudaFuncAttributeMaxDynamicSharedMemorySize, SMEM_BYTES);

    zero_cnt<<<1, 1>>>();
    prep_in<<<(M_TOT * DIN) / 1024, 256>>>(inputs);
    prep_w<<<(DH * DIN) / 1024, 256>>>(W);

    dim3 ggrid(M_TOT / 128, DH / 128);   // (256, 4)
    gemm_tf32<<<ggrid, 256, SMEM_BYTES>>>(bias, Xs);

    scan2f<<<512, 256>>>(Xs, thr, out);
    patch<<<2048, 32>>>(inputs, W, bias, thr, out);
}

// round 15
// speedup vs baseline: 2.8008x; 2.0187x over previous
#include <cuda_runtime.h>
#include <cstdint>

#define BATCH 32
#define T     1024
#define DIN   512
#define DH    512
#define M_TOT (BATCH * T)   // 32768

// scratch: X~ (64MB)
__device__ float g_X[(size_t)M_TOT * DH];

#define WLCAP 262144
__device__ int g_cnt;
__device__ int g_wl[WLCAP];

#define DELTA 1.2e-3f

// ---------------------------------------------------------------------------
__device__ __forceinline__ uint32_t smem_u32(const void* p) {
    uint32_t a;
    asm("{ .reg .u64 t; cvta.to.shared.u64 t, %1; cvt.u32.u64 %0, t; }"
        : "=r"(a) : "l"(p));
    return a;
}
#define CP_ASYNC16(sa, gp) \
    asm volatile("cp.async.cg.shared.global [%0], [%1], 16;" :: "r"(sa), "l"(gp))
#define CP_COMMIT() asm volatile("cp.async.commit_group;" ::: "memory")
#define CP_WAIT(n)  asm volatile("cp.async.wait_group %0;" :: "n"(n) : "memory")

__device__ __forceinline__ float cvt_tf32(float x) {
    uint32_t b;
    asm("cvt.rna.tf32.f32 %0, %1;" : "=r"(b) : "f"(x));
    return __uint_as_float(b);
}
__device__ __forceinline__ void mma_tf32(float c[4], const float a[4], const float b[2]) {
    asm volatile(
        "mma.sync.aligned.m16n8k8.row.col.f32.tf32.tf32.f32 "
        "{%0,%1,%2,%3}, {%4,%5,%6,%7}, {%8,%9}, {%0,%1,%2,%3};"
        : "+f"(c[0]), "+f"(c[1]), "+f"(c[2]), "+f"(c[3])
        : "r"(__float_as_uint(a[0])), "r"(__float_as_uint(a[1])),
          "r"(__float_as_uint(a[2])), "r"(__float_as_uint(a[3])),
          "r"(__float_as_uint(b[0])), "r"(__float_as_uint(b[1])));
}

// ---------------------------------------------------------------------------
// Single-pass tf32 GEMM with FUSED rounding: raw A/W staged via cp.async,
// cvt.rna.tf32 applied to fragments in registers (bitwise-identical X~ to the
// separate-prep version). 128x128 CTA tile, 8 warps, K-chunk 32, dbl buffer.
// ---------------------------------------------------------------------------
#define BK      32
#define NCHUNK  (DIN / BK)
#define SROW    36
#define A_OFF   0
#define B_OFF   (128 * SROW)
#define BUF_FL  (2 * 128 * SROW)
#define SMEM_BYTES (2 * BUF_FL * 4)   // 73728

__device__ __forceinline__ void issue_chunk(const float* __restrict__ A,
                                            const float* __restrict__ W,
                                            uint32_t sbuf, int bm, int bn,
                                            int k0, int tid)
{
#pragma unroll
    for (int q = 0; q < 4; q++) {
        int u   = tid + q * 256;
        int row = u >> 3;
        int seg = u & 7;
        CP_ASYNC16(sbuf + A_OFF * 4 + row * (SROW * 4) + seg * 16,
                   A + (size_t)(bm + row) * DIN + k0 + seg * 4);
        CP_ASYNC16(sbuf + B_OFF * 4 + row * (SROW * 4) + seg * 16,
                   W + (size_t)(bn + row) * DIN + k0 + seg * 4);
    }
}

__global__ __launch_bounds__(256, 2)
void gemm_tf32(const float* __restrict__ A, const float* __restrict__ W,
               const float* __restrict__ bias, float* __restrict__ X)
{
    extern __shared__ float sm[];
    const int tid  = threadIdx.x;
    const int lane = tid & 31;
    const int wid  = tid >> 5;
    const int g    = lane >> 2;
    const int tg   = lane & 3;
    const int wm   = wid >> 2;
    const int wn   = wid & 3;
    const int bm   = blockIdx.x * 128;
    const int bn   = blockIdx.y * 128;

    if (bm == 0 && bn == 0 && tid == 0) g_cnt = 0;   // fused zero_cnt

    const uint32_t sb0 = smem_u32(sm);

    float acc[4][4][4];
#pragma unroll
    for (int i = 0; i < 4; i++)
#pragma unroll
        for (int j = 0; j < 4; j++)
#pragma unroll
            for (int r = 0; r < 4; r++) acc[i][j][r] = 0.0f;

    issue_chunk(A, W, sb0, bm, bn, 0, tid);
    CP_COMMIT();

    for (int c = 0; c < NCHUNK; c++) {
        if (c + 1 < NCHUNK) {
            issue_chunk(A, W, sb0 + ((c + 1) & 1) * (BUF_FL * 4), bm, bn,
                        (c + 1) * BK, tid);
            CP_COMMIT();
            CP_WAIT(1);
        } else {
            CP_WAIT(0);
        }
        __syncthreads();

        const float* As = sm + (c & 1) * BUF_FL + A_OFF;
        const float* Bs = sm + (c & 1) * BUF_FL + B_OFF;

#pragma unroll
        for (int ks = 0; ks < 4; ks++) {
            const int kk = ks * 8;
            float a[4][4], b[4][2];
#pragma unroll
            for (int i = 0; i < 4; i++) {
                int row = wm * 64 + i * 16 + g;
                a[i][0] = cvt_tf32(As[(row     ) * SROW + kk + tg    ]);
                a[i][1] = cvt_tf32(As[(row +  8) * SROW + kk + tg    ]);
                a[i][2] = cvt_tf32(As[(row     ) * SROW + kk + tg + 4]);
                a[i][3] = cvt_tf32(As[(row +  8) * SROW + kk + tg + 4]);
            }
#pragma unroll
            for (int j = 0; j < 4; j++) {
                int n = wn * 32 + j * 8 + g;
                b[j][0] = cvt_tf32(Bs[n * SROW + kk + tg    ]);
                b[j][1] = cvt_tf32(Bs[n * SROW + kk + tg + 4]);
            }
#pragma unroll
            for (int i = 0; i < 4; i++)
#pragma unroll
                for (int j = 0; j < 4; j++)
                    mma_tf32(acc[i][j], a[i], b[j]);
        }
        __syncthreads();
    }

#pragma unroll
    for (int j = 0; j < 4; j++) {
        int col = bn + wn * 32 + j * 8 + tg * 2;
        float b0 = bias[col], b1 = bias[col + 1];
#pragma unroll
        for (int i = 0; i < 4; i++) {
            int row = bm + wm * 64 + i * 16 + g;
            float2 v0 = { acc[i][j][0] + b0, acc[i][j][1] + b1 };
            float2 v1 = { acc[i][j][2] + b0, acc[i][j][3] + b1 };
            *(float2*)(X + (size_t)row * DH + col)       = v0;
            *(float2*)(X + (size_t)(row + 8) * DH + col) = v1;
        }
    }
}

// ---------------------------------------------------------------------------
// Chunk-parallel scan on X~ with threshold + borderline flagging.
// ---------------------------------------------------------------------------
__global__ __launch_bounds__(256)
void scan2f(const float* __restrict__ X, const float* __restrict__ thr_p,
            float* __restrict__ out)
{
    const int bc    = blockIdx.x;
    const int b     = bc >> 4;
    const int chunk = (bc >> 1) & 7;
    const int half  = bc & 1;
    const int h     = half * 256 + threadIdx.x;

    const float AL  = 0.36787944117144233f;
    const float OMB = 1.0f - AL;
    const float thr = thr_p[0];

    const float* xp = X   + (size_t)b * T * DH + h;
    float*       op = out + (size_t)b * T * DH + h;

    const int t0 = chunk * 128;
    const int w0 = (t0 >= 96) ? (t0 - 96) : 0;
    const int base_lin = (b * T) * DH + h;

    float s = 0.0f, m = 0.0f;

    for (int t = w0; t < t0; t += 8) {
        float x[8];
#pragma unroll
        for (int u = 0; u < 8; u++) x[u] = xp[(size_t)(t + u) * DH];
#pragma unroll
        for (int u = 0; u < 8; u++) {
            s = fmaf(AL, s, x[u]);
            m = fmaf(AL, m, OMB * s);
        }
    }
    for (int t = t0; t < t0 + 128; t += 8) {
        float x[8], sp[8];
#pragma unroll
        for (int u = 0; u < 8; u++) x[u] = xp[(size_t)(t + u) * DH];
#pragma unroll
        for (int u = 0; u < 8; u++) {
            s = fmaf(AL, s, x[u]);
            m = fmaf(AL, m, OMB * s);
            float d = m - thr;
            sp[u] = (d > 0.0f) ? 1.0f : 0.0f;
            if (fabsf(d) < DELTA) {
                int idx = atomicAdd(&g_cnt, 1);
                if (idx < WLCAP) g_wl[idx] = base_lin + (t + u) * DH;
            }
        }
#pragma unroll
        for (int u = 0; u < 8; u++) op[(size_t)(t + u) * DH] = sp[u];
    }
}

// ---------------------------------------------------------------------------
// Patch: recompute flagged elements with the R1-exact float-op sequence
// (bitwise-validated mechanism, R8). One warp per item, 48-step warmup
// (window <= 49 rows; truncation-tail rounding risk ~1e-12). A-tiles are
// cp.async DOUBLE-BUFFERED (latency hidden); final scan reads a smem-staged
// xv array (LDS broadcast) instead of 3 shfl per step.
// ---------------------------------------------------------------------------
#define PROWS 49
#define PSTR  68     // floats per smem row (64 + 4; 272B, 16B aligned)

__global__ __launch_bounds__(32)
void patch(const float* __restrict__ X, const float* __restrict__ W,
           const float* __restrict__ bias, const float* __restrict__ thr_p,
           float* __restrict__ OUT)
{
    __shared__ __align__(16) float As[2][PROWS * PSTR];  // 2 x 13328 B
    __shared__ __align__(16) float Ws[DIN];              // 2048 B
    __shared__ float sx[64];

    const int lane = threadIdx.x;
    const int cnt  = min(g_cnt, WLCAP);

    const float AL  = 0.36787944117144233f;
    const float OMB = 1.0f - AL;
    const float thr = thr_p[0];

    const uint32_t as_base = smem_u32(&As[0][0]);

    for (int it = blockIdx.x; it < cnt; it += gridDim.x) {
        int lin = g_wl[it];
        int h  = lin & (DH - 1);
        int bt = lin >> 9;
        int t  = bt & (T - 1);
        int b  = bt >> 10;

        int tw = (t >= 48) ? (t - 48) : 0;
        int nT = t - tw + 1;   // <= 49

        // stage W row (coalesced)
#pragma unroll
        for (int q = 0; q < 4; q++) {
            int k = q * 128 + lane * 4;
            *(float4*)&Ws[k] = *(const float4*)(W + (size_t)h * DIN + k);
        }
        float bh = bias[h];

        // lane owns dot rows lane, lane+32 (clamped to window)
        int r_ln[2];
#pragma unroll
        for (int u = 0; u < 2; u++) {
            int tp = tw + lane + u * 32;
            r_ln[u] = ((tp <= t) ? tp : t) - tw;
        }

        const float* xbase = X + ((size_t)b * T + tw) * DIN;
        const int nld = nT * 16;   // float4 loads per tile

        // prologue: stage tile 0 into buffer 0
        for (int u = lane; u < nld; u += 32) {
            int r = u >> 4, cc = u & 15;
            CP_ASYNC16(as_base + (r * PSTR + cc * 4) * 4,
                       xbase + (size_t)r * DIN + cc * 4);
        }
        CP_COMMIT();

        float acc[2] = {0.0f, 0.0f};

        for (int kt = 0; kt < 8; kt++) {
            if (kt + 1 < 8) {
                uint32_t dstb = as_base + ((kt + 1) & 1) * (PROWS * PSTR * 4);
                const float* src = xbase + (kt + 1) * 64;
                for (int u = lane; u < nld; u += 32) {
                    int r = u >> 4, cc = u & 15;
                    CP_ASYNC16(dstb + (r * PSTR + cc * 4) * 4,
                               src + (size_t)r * DIN + cc * 4);
                }
                CP_COMMIT();
                CP_WAIT(1);
            } else {
                CP_WAIT(0);
            }
            __syncwarp();

            const float* Ab = As[kt & 1];
            const float* wr = &Ws[kt * 64];
#pragma unroll
            for (int u = 0; u < 2; u++) {
                const float* ar = &Ab[r_ln[u] * PSTR];
                float a = acc[u];
#pragma unroll
                for (int cq = 0; cq < 16; cq++) {
                    float4 a4 = *(const float4*)&ar[cq * 4];
                    float4 w4 = *(const float4*)&wr[cq * 4];
                    a = fmaf(a4.x, w4.x, a);
                    a = fmaf(a4.y, w4.y, a);
                    a = fmaf(a4.z, w4.z, a);
                    a = fmaf(a4.w, w4.w, a);
                }
                acc[u] = a;
            }
            __syncwarp();
        }

        // distribute xv via smem, then exact scan (all lanes, LDS broadcast)
        sx[lane]      = acc[0] + bh;
        sx[lane + 32] = acc[1] + bh;
        __syncwarp();

        float s = 0.0f, m = 0.0f;
        for (int q = 0; q < nT; q++) {
            float x = sx[q];
            s = fmaf(AL, s, x);
            m = fmaf(AL, m, OMB * s);
        }
        if (lane == 0)
            OUT[lin] = (m > thr) ? 1.0f : 0.0f;
        __syncwarp();
    }
}

// ---------------------------------------------------------------------------
extern "C" void kernel_launch(void* const* d_in, const int* in_sizes, int n_in,
                              void* d_out, int out_size)
{
    const float* inputs = (const float*)d_in[0];
    const float* W      = (const float*)d_in[1];
    const float* bias   = (const float*)d_in[2];
    const float* thr    = (const float*)d_in[3];
    float*       out    = (float*)d_out;

    float* Xs;
    cudaGetSymbolAddress((void**)&Xs, g_X);

    cudaFuncSetAttribute(gemm_tf32, cudaFuncAttributeMaxDynamicSharedMemorySize, SMEM_BYTES);

    dim3 ggrid(M_TOT / 128, DH / 128);   // (256, 4)
    gemm_tf32<<<ggrid, 256, SMEM_BYTES>>>(inputs, W, bias, Xs);

    scan2f<<<512, 256>>>(Xs, thr, out);
    patch<<<4096, 32>>>(inputs, W, bias, thr, out);
}

// round 16
// speedup vs baseline: 3.1472x; 1.1237x over previous
#include <cuda_runtime.h>
#include <cstdint>

#define BATCH 32
#define T     1024
#define DIN   512
#define DH    512
#define M_TOT (BATCH * T)   // 32768

// scratch: X~ (64MB)
__device__ float g_X[(size_t)M_TOT * DH];

#define WLCAP 262144
__device__ int g_cnt;
__device__ int g_wl[WLCAP];

#define DELTA 1.2e-3f

// ---------------------------------------------------------------------------
__device__ __forceinline__ uint32_t smem_u32(const void* p) {
    uint32_t a;
    asm("{ .reg .u64 t; cvta.to.shared.u64 t, %1; cvt.u32.u64 %0, t; }"
        : "=r"(a) : "l"(p));
    return a;
}
#define CP_ASYNC16(sa, gp) \
    asm volatile("cp.async.cg.shared.global [%0], [%1], 16;" :: "r"(sa), "l"(gp))
#define CP_COMMIT() asm volatile("cp.async.commit_group;" ::: "memory")
#define CP_WAIT(n)  asm volatile("cp.async.wait_group %0;" :: "n"(n) : "memory")

__device__ __forceinline__ float cvt_tf32(float x) {
    uint32_t b;
    asm("cvt.rna.tf32.f32 %0, %1;" : "=r"(b) : "f"(x));
    return __uint_as_float(b);
}
__device__ __forceinline__ void mma_tf32(float c[4], const float a[4], const float b[2]) {
    asm volatile(
        "mma.sync.aligned.m16n8k8.row.col.f32.tf32.tf32.f32 "
        "{%0,%1,%2,%3}, {%4,%5,%6,%7}, {%8,%9}, {%0,%1,%2,%3};"
        : "+f"(c[0]), "+f"(c[1]), "+f"(c[2]), "+f"(c[3])
        : "r"(__float_as_uint(a[0])), "r"(__float_as_uint(a[1])),
          "r"(__float_as_uint(a[2])), "r"(__float_as_uint(a[3])),
          "r"(__float_as_uint(b[0])), "r"(__float_as_uint(b[1])));
}

// ---------------------------------------------------------------------------
// tf32 GEMM, fragment-permuted smem layout:
//  - staging: LDG float4 -> cvt.rna.tf32 (once per element) -> scatter STS
//    into per-fragment groups. Register double-buffered (no cp.async).
//  - mainloop: A frag = one ld.shared.v4, B frag = one ld.shared.v2.
// Math/accumulation order identical to prior rounds -> bitwise-same X~.
// A groups: [rowblock(8) x kstep(4)] stride 132 floats, elem at lane*4+reg.
// B groups: [nblock(16) x kstep(4)] stride 66 floats, elem at lane*2+reg.
// ---------------------------------------------------------------------------
#define AGRP   132
#define BGRP   66
#define A_FL   (32 * AGRP)          // 4224 floats
#define B_FL   (64 * BGRP)          // 4224 floats
#define BUF_FL (A_FL + B_FL)        // 8448 floats per buffer
#define SMEM_BYTES (2 * BUF_FL * 4) // 67584

__global__ __launch_bounds__(256, 2)
void gemm_tf32(const float* __restrict__ A, const float* __restrict__ W,
               const float* __restrict__ bias, float* __restrict__ X)
{
    extern __shared__ float sm[];
    const int tid  = threadIdx.x;
    const int lane = tid & 31;
    const int wid  = tid >> 5;
    const int g    = lane >> 2;
    const int tg   = lane & 3;
    const int wm   = wid >> 2;
    const int wn   = wid & 3;
    const int bm   = blockIdx.x * 128;
    const int bn   = blockIdx.y * 128;

    if (bm == 0 && bn == 0 && tid == 0) g_cnt = 0;   // fused zero_cnt

    float acc[4][4][4];
#pragma unroll
    for (int i = 0; i < 4; i++)
#pragma unroll
        for (int j = 0; j < 4; j++)
#pragma unroll
            for (int r = 0; r < 4; r++) acc[i][j][r] = 0.0f;

    // staging unit mapping: u = q*256+tid; row = u>>3, k4 = (u&7)*4
    const int srow = tid >> 3;          // base row for q=0 (rows advance by 32/q)
    const int sk4  = (tid & 7) << 2;

    float4 ra[4], rb[4];
#pragma unroll
    for (int q = 0; q < 4; q++) {
        int row = q * 32 + srow;
        ra[q] = *(const float4*)(A + (size_t)(bm + row) * DIN + sk4);
        rb[q] = *(const float4*)(W + (size_t)(bn + row) * DIN + sk4);
    }

    for (int c = 0; c < 16; c++) {
        float* buf = sm + (c & 1) * BUF_FL;

        // scatter-store with fused tf32 rounding
        {
            const int ks = sk4 >> 3;
            const int th = (sk4 >> 2) & 1;
#pragma unroll
            for (int q = 0; q < 4; q++) {
                int row = q * 32 + srow;
                int blk = row >> 4, rr = row & 15;
                int ag = rr & 7, hi = rr >> 3;
                float* abase = buf + (blk * 4 + ks) * AGRP + ag * 16 + hi + 2 * th;
                float va[4] = {ra[q].x, ra[q].y, ra[q].z, ra[q].w};
#pragma unroll
                for (int e = 0; e < 4; e++) abase[4 * e] = cvt_tf32(va[e]);

                int nb = row >> 3, gg = row & 7;
                float* bbase = buf + A_FL + (nb * 4 + ks) * BGRP + gg * 8 + th;
                float vb[4] = {rb[q].x, rb[q].y, rb[q].z, rb[q].w};
#pragma unroll
                for (int e = 0; e < 4; e++) bbase[2 * e] = cvt_tf32(vb[e]);
            }
        }
        __syncthreads();

        if (c + 1 < 16) {
            int k0 = (c + 1) * 32;
#pragma unroll
            for (int q = 0; q < 4; q++) {
                int row = q * 32 + srow;
                ra[q] = *(const float4*)(A + (size_t)(bm + row) * DIN + k0 + sk4);
                rb[q] = *(const float4*)(W + (size_t)(bn + row) * DIN + k0 + sk4);
            }
        }

        // compute: vectorized fragment loads
#pragma unroll
        for (int ks = 0; ks < 4; ks++) {
            float a[4][4], b[4][2];
#pragma unroll
            for (int i = 0; i < 4; i++) {
                float4 av = *(const float4*)(buf + ((wm * 4 + i) * 4 + ks) * AGRP + lane * 4);
                a[i][0] = av.x; a[i][1] = av.y; a[i][2] = av.z; a[i][3] = av.w;
            }
#pragma unroll
            for (int j = 0; j < 4; j++) {
                float2 bv = *(const float2*)(buf + A_FL + ((wn * 4 + j) * 4 + ks) * BGRP + lane * 2);
                b[j][0] = bv.x; b[j][1] = bv.y;
            }
#pragma unroll
            for (int i = 0; i < 4; i++)
#pragma unroll
                for (int j = 0; j < 4; j++)
                    mma_tf32(acc[i][j], a[i], b[j]);
        }
        __syncthreads();
    }

#pragma unroll
    for (int j = 0; j < 4; j++) {
        int col = bn + wn * 32 + j * 8 + tg * 2;
        float b0 = bias[col], b1 = bias[col + 1];
#pragma unroll
        for (int i = 0; i < 4; i++) {
            int row = bm + wm * 64 + i * 16 + g;
            float2 v0 = { acc[i][j][0] + b0, acc[i][j][1] + b1 };
            float2 v1 = { acc[i][j][2] + b0, acc[i][j][3] + b1 };
            *(float2*)(X + (size_t)row * DH + col)       = v0;
            *(float2*)(X + (size_t)(row + 8) * DH + col) = v1;
        }
    }
}

// ---------------------------------------------------------------------------
// Chunk-parallel scan on X~ with threshold + borderline flagging.
// ---------------------------------------------------------------------------
__global__ __launch_bounds__(256)
void scan2f(const float* __restrict__ X, const float* __restrict__ thr_p,
            float* __restrict__ out)
{
    const int bc    = blockIdx.x;
    const int b     = bc >> 4;
    const int chunk = (bc >> 1) & 7;
    const int half  = bc & 1;
    const int h     = half * 256 + threadIdx.x;

    const float AL  = 0.36787944117144233f;
    const float OMB = 1.0f - AL;
    const float thr = thr_p[0];

    const float* xp = X   + (size_t)b * T * DH + h;
    float*       op = out + (size_t)b * T * DH + h;

    const int t0 = chunk * 128;
    const int w0 = (t0 >= 96) ? (t0 - 96) : 0;
    const int base_lin = (b * T) * DH + h;

    float s = 0.0f, m = 0.0f;

    for (int t = w0; t < t0; t += 8) {
        float x[8];
#pragma unroll
        for (int u = 0; u < 8; u++) x[u] = xp[(size_t)(t + u) * DH];
#pragma unroll
        for (int u = 0; u < 8; u++) {
            s = fmaf(AL, s, x[u]);
            m = fmaf(AL, m, OMB * s);
        }
    }
    for (int t = t0; t < t0 + 128; t += 8) {
        float x[8], sp[8];
#pragma unroll
        for (int u = 0; u < 8; u++) x[u] = xp[(size_t)(t + u) * DH];
#pragma unroll
        for (int u = 0; u < 8; u++) {
            s = fmaf(AL, s, x[u]);
            m = fmaf(AL, m, OMB * s);
            float d = m - thr;
            sp[u] = (d > 0.0f) ? 1.0f : 0.0f;
            if (fabsf(d) < DELTA) {
                int idx = atomicAdd(&g_cnt, 1);
                if (idx < WLCAP) g_wl[idx] = base_lin + (t + u) * DH;
            }
        }
#pragma unroll
        for (int u = 0; u < 8; u++) op[(size_t)(t + u) * DH] = sp[u];
    }
}

// ---------------------------------------------------------------------------
// Patch: recompute flagged elements with the R1-exact float-op sequence.
// 28-step warmup (window <= 29 rows; discarded tail weight ~2e-11 ->
// decision-change probability ~8e-5 across all items). cp.async double-
// buffered k-tiles; LDS-broadcast final scan.
// ---------------------------------------------------------------------------
#define PROWS 29
#define PSTR  68     // floats per smem row (64 + 4; 272B, 16B aligned)

__global__ __launch_bounds__(32)
void patch(const float* __restrict__ X, const float* __restrict__ W,
           const float* __restrict__ bias, const float* __restrict__ thr_p,
           float* __restrict__ OUT)
{
    __shared__ __align__(16) float As[2][PROWS * PSTR];  // 2 x 7888 B
    __shared__ __align__(16) float Ws[DIN];              // 2048 B
    __shared__ float sx[32];

    const int lane = threadIdx.x;
    const int cnt  = min(g_cnt, WLCAP);

    const float AL  = 0.36787944117144233f;
    const float OMB = 1.0f - AL;
    const float thr = thr_p[0];

    const uint32_t as_base = smem_u32(&As[0][0]);

    for (int it = blockIdx.x; it < cnt; it += gridDim.x) {
        int lin = g_wl[it];
        int h  = lin & (DH - 1);
        int bt = lin >> 9;
        int t  = bt & (T - 1);
        int b  = bt >> 10;

        int tw = (t >= 28) ? (t - 28) : 0;
        int nT = t - tw + 1;   // <= 29

        // stage W row (coalesced)
#pragma unroll
        for (int q = 0; q < 4; q++) {
            int k = q * 128 + lane * 4;
            *(float4*)&Ws[k] = *(const float4*)(W + (size_t)h * DIN + k);
        }
        float bh = bias[h];

        // lane owns dot for window row lane (clamped)
        int r_ln = ((tw + lane <= t) ? (tw + lane) : t) - tw;

        const float* xbase = X + ((size_t)b * T + tw) * DIN;
        const int nld = nT * 16;   // float4 loads per tile

        for (int u = lane; u < nld; u += 32) {
            int r = u >> 4, cc = u & 15;
            CP_ASYNC16(as_base + (r * PSTR + cc * 4) * 4,
                       xbase + (size_t)r * DIN + cc * 4);
        }
        CP_COMMIT();

        float acc = 0.0f;

        for (int kt = 0; kt < 8; kt++) {
            if (kt + 1 < 8) {
                uint32_t dstb = as_base + ((kt + 1) & 1) * (PROWS * PSTR * 4);
                const float* src = xbase + (kt + 1) * 64;
                for (int u = lane; u < nld; u += 32) {
                    int r = u >> 4, cc = u & 15;
                    CP_ASYNC16(dstb + (r * PSTR + cc * 4) * 4,
                               src + (size_t)r * DIN + cc * 4);
                }
                CP_COMMIT();
                CP_WAIT(1);
            } else {
                CP_WAIT(0);
            }
            __syncwarp();

            const float* ar = &As[kt & 1][r_ln * PSTR];
            const float* wr = &Ws[kt * 64];
            float a = acc;
#pragma unroll
            for (int cq = 0; cq < 16; cq++) {
                float4 a4 = *(const float4*)&ar[cq * 4];
                float4 w4 = *(const float4*)&wr[cq * 4];
                a = fmaf(a4.x, w4.x, a);
                a = fmaf(a4.y, w4.y, a);
                a = fmaf(a4.z, w4.z, a);
                a = fmaf(a4.w, w4.w, a);
            }
            acc = a;
            __syncwarp();
        }

        sx[lane] = acc + bh;
        __syncwarp();

        float s = 0.0f, m = 0.0f;
        for (int q = 0; q < nT; q++) {
            float x = sx[q];
            s = fmaf(AL, s, x);
            m = fmaf(AL, m, OMB * s);
        }
        if (lane == 0)
            OUT[lin] = (m > thr) ? 1.0f : 0.0f;
        __syncwarp();
    }
}

// ---------------------------------------------------------------------------
extern "C" void kernel_launch(void* const* d_in, const int* in_sizes, int n_in,
                              void* d_out, int out_size)
{
    const float* inputs = (const float*)d_in[0];
    const float* W      = (const float*)d_in[1];
    const float* bias   = (const float*)d_in[2];
    const float* thr    = (const float*)d_in[3];
    float*       out    = (float*)d_out;

    float* Xs;
    cudaGetSymbolAddress((void**)&Xs, g_X);

    cudaFuncSetAttribute(gemm_tf32, cudaFuncAttributeMaxDynamicSharedMemorySize, SMEM_BYTES);

    dim3 ggrid(M_TOT / 128, DH / 128);   // (256, 4)
    gemm_tf32<<<ggrid, 256, SMEM_BYTES>>>(inputs, W, bias, Xs);

    scan2f<<<512, 256>>>(Xs, thr, out);
    patch<<<4096, 32>>>(inputs, W, bias, thr, out);
}